// round 9
// baseline (speedup 1.0000x reference)
#include <cuda_runtime.h>

#define TSTEPS  100
#define FDIM    3
#define TILE_B  64       // rows per CTA (2 groups x 32)
#define NTHREADS 256     // 2 groups x 128 threads
#define GROWS   32       // rows per group

#define KS   288         // floats per k-row of sU/sW (8 uo-blocks * 36)
#define UOS  36
#define HP   48          // h tile stride: [unit][row] rows 0..31 + pad

#define OFF_U 0                        // 64*288 = 18432
#define OFF_W 18432                    // 864
#define OFF_B (18432+864)              // 288
#define OFF_H (OFF_B+288)              // 2 * 64*48 = 6144
#define SMEM_FLOATS (OFF_H + 2*64*HP)
#define SMEM_BYTES  (SMEM_FLOATS*4)    // ~100.5 KB -> 2 CTAs/SM

// head phase reuses dead sU region
#define HW1 0
#define HB1 4096
#define HW2 4160
#define HB2 4480
#define HH1 4488                       // 2 * 64*48 = 6144 (ends 10632 < 18432)

__device__ __forceinline__ unsigned long long pack2(float x) {
    unsigned long long r;
    asm("mov.b64 %0, {%1, %1};" : "=l"(r) : "f"(x));
    return r;
}
__device__ __forceinline__ void fma2(unsigned long long& d,
                                     unsigned long long a,
                                     unsigned long long b) {
    asm("fma.rn.f32x2 %0, %1, %2, %0;" : "+l"(d) : "l"(a), "l"(b));
}
__device__ __forceinline__ float2 unpack2(unsigned long long v) {
    float2 f;
    asm("mov.b64 {%0, %1}, %2;" : "=f"(f.x), "=f"(f.y) : "l"(v));
    return f;
}
__device__ __forceinline__ float ex2f_(float x) {
    float y; asm("ex2.approx.f32 %0, %1;" : "=f"(y) : "f"(x)); return y;
}
__device__ __forceinline__ float rcpf_(float x) {
    float y; asm("rcp.approx.f32 %0, %1;" : "=f"(y) : "f"(x)); return y;
}
__device__ __forceinline__ float sigf_(float x) {
    return rcpf_(1.0f + ex2f_(-1.4426950408889634f * x));
}
__device__ __forceinline__ float tanhf_(float x) {
    return 1.0f - 2.0f * rcpf_(1.0f + ex2f_(2.8853900817779268f * x));
}
__device__ __forceinline__ void barg(int id) {
    asm volatile("bar.sync %0, 128;" :: "r"(id) : "memory");
}

__global__ void __launch_bounds__(NTHREADS, 2)
lstm_kernel(const float* __restrict__ x,  const float* __restrict__ W,
            const float* __restrict__ U,  const float* __restrict__ b,
            const float* __restrict__ W1, const float* __restrict__ b1,
            const float* __restrict__ W2, const float* __restrict__ b2,
            float* __restrict__ out, int B)
{
    extern __shared__ float sm[];
    const int tid = threadIdx.x;
    const int g   = tid >> 7;          // group 0/1
    const int lt  = tid & 127;
    const int uo  = lt >> 4;           // 0..7  : 8 units each
    const int rq  = lt & 15;           // 0..15 : rows rq and rq+16
    const int barid = 1 + g;

    // ---- stage U/W/b skewed: sU[k*KS + uo*UOS + i*4 + gate] ----
    for (int idx = tid; idx < 64 * 256; idx += NTHREADS) {
        int k = idx >> 8, rem = idx & 255, gate = rem >> 6, u = rem & 63;
        sm[OFF_U + k * KS + (u >> 3) * UOS + (u & 7) * 4 + gate] = U[idx];
    }
    for (int idx = tid; idx < 3 * 256; idx += NTHREADS) {
        int f = idx >> 8, rem = idx & 255, gate = rem >> 6, u = rem & 63;
        sm[OFF_W + f * KS + (u >> 3) * UOS + (u & 7) * 4 + gate] = W[idx];
    }
    for (int idx = tid; idx < 256; idx += NTHREADS) {
        int gate = idx >> 6, u = idx & 63;
        sm[OFF_B + (u >> 3) * UOS + (u & 7) * 4 + gate] = b[idx];
    }
    for (int idx = tid; idx < 2 * 64 * HP; idx += NTHREADS) sm[OFF_H + idx] = 0.0f;

    float* sHg = sm + OFF_H + g * (64 * HP);   // transposed h: [unit][row]

    float c[16];
    #pragma unroll
    for (int z = 0; z < 16; z++) c[z] = 0.0f;

    const int rowbase = blockIdx.x * TILE_B + g * GROWS;
    int r0 = rowbase + rq;        if (r0 >= B) r0 = B - 1;
    int r1 = rowbase + rq + 16;   if (r1 >= B) r1 = B - 1;
    const float* x0p_ = x + (size_t)r0 * (TSTEPS * FDIM);
    const float* x1p_ = x + (size_t)r1 * (TSTEPS * FDIM);

    __syncthreads();

    unsigned long long aif[16], ago[16];

    for (int t = 0; t < TSTEPS; t++) {
        const float xa0 = __ldg(x0p_ + t*3 + 0);
        const float xa1 = __ldg(x0p_ + t*3 + 1);
        const float xa2 = __ldg(x0p_ + t*3 + 2);
        const float xb0 = __ldg(x1p_ + t*3 + 0);
        const float xb1 = __ldg(x1p_ + t*3 + 1);
        const float xb2 = __ldg(x1p_ + t*3 + 2);
        const bool m0 = (xa0 != 0.0f) || (xa1 != 0.0f) || (xa2 != 0.0f);
        const bool m1 = (xb0 != 0.0f) || (xb1 != 0.0f) || (xb2 != 0.0f);
        const unsigned long long pa0 = pack2(xa0), pa1 = pack2(xa1), pa2 = pack2(xa2);
        const unsigned long long pb0 = pack2(xb0), pb1 = pack2(xb1), pb2 = pack2(xb2);

        // acc = bias + x @ W
        #pragma unroll
        for (int i = 0; i < 8; i++) {
            ulonglong2 bb = *(const ulonglong2*)(sm + OFF_B + uo*UOS + i*4);
            ulonglong2 w0 = *(const ulonglong2*)(sm + OFF_W + 0*KS + uo*UOS + i*4);
            ulonglong2 w1 = *(const ulonglong2*)(sm + OFF_W + 1*KS + uo*UOS + i*4);
            ulonglong2 w2 = *(const ulonglong2*)(sm + OFF_W + 2*KS + uo*UOS + i*4);
            unsigned long long a0 = bb.x, a1 = bb.y;
            fma2(a0, pa0, w0.x); fma2(a1, pa0, w0.y);
            fma2(a0, pa1, w1.x); fma2(a1, pa1, w1.y);
            fma2(a0, pa2, w2.x); fma2(a1, pa2, w2.y);
            aif[i] = a0; ago[i] = a1;
            unsigned long long b0 = bb.x, b1 = bb.y;
            fma2(b0, pb0, w0.x); fma2(b1, pb0, w0.y);
            fma2(b0, pb1, w1.x); fma2(b1, pb1, w1.y);
            fma2(b0, pb2, w2.x); fma2(b1, pb2, w2.y);
            aif[8+i] = b0; ago[8+i] = b1;
        }

        // z += h @ U : per k, 2 broadcast LDS.32 (h) + 8 LDS.128 (U) + 32 FFMA2
        #pragma unroll 4
        for (int k = 0; k < 64; k++) {
            const unsigned long long h0 = pack2(sHg[k * HP + rq]);
            const unsigned long long h1 = pack2(sHg[k * HP + rq + 16]);
            const float* uk = sm + OFF_U + k * KS + uo * UOS;
            #pragma unroll
            for (int i = 0; i < 8; i++) {
                ulonglong2 uv = *(const ulonglong2*)(uk + i * 4);
                fma2(aif[i],   h0, uv.x); fma2(ago[i],   h0, uv.y);
                fma2(aif[8+i], h1, uv.x); fma2(ago[8+i], h1, uv.y);
            }
        }

        barg(barid);   // reads of old h done (group scope)

        #pragma unroll
        for (int i = 0; i < 8; i++) {
            const int u = uo * 8 + i;
            {
                float2 zif = unpack2(aif[i]);
                float2 zgo = unpack2(ago[i]);
                float ig = sigf_(zif.x), fg = sigf_(zif.y);
                float gg = tanhf_(zgo.x), og = sigf_(zgo.y);
                float cn = fg * c[i] + ig * gg;
                float hn = og * tanhf_(cn);
                if (m0) { c[i] = cn; sHg[u * HP + rq] = hn; }
            }
            {
                float2 zif = unpack2(aif[8+i]);
                float2 zgo = unpack2(ago[8+i]);
                float ig = sigf_(zif.x), fg = sigf_(zif.y);
                float gg = tanhf_(zgo.x), og = sigf_(zgo.y);
                float cn = fg * c[8+i] + ig * gg;
                float hn = og * tanhf_(cn);
                if (m1) { c[8+i] = cn; sHg[u * HP + rq + 16] = hn; }
            }
        }

        barg(barid);   // new h visible
    }

    // ---------------- head: relu(h@W1+b1) @ W2 + b2, softmax ----------------
    __syncthreads();
    for (int idx = tid; idx < 4096; idx += NTHREADS) sm[HW1 + idx] = W1[idx];
    for (int idx = tid; idx < 64;   idx += NTHREADS) sm[HB1 + idx] = b1[idx];
    for (int idx = tid; idx < 320;  idx += NTHREADS) sm[HW2 + idx] = W2[idx];
    if (tid < 5) sm[HB2 + tid] = b2[tid];
    __syncthreads();

    float* sH1g = sm + HH1 + g * (64 * HP);
    {
        float acc[16];
        #pragma unroll
        for (int i = 0; i < 8; i++) {
            float bv = sm[HB1 + uo * 8 + i];
            acc[i] = bv; acc[8+i] = bv;
        }
        for (int k = 0; k < 64; k++) {
            float h0 = sHg[k * HP + rq];
            float h1 = sHg[k * HP + rq + 16];
            #pragma unroll
            for (int i = 0; i < 8; i++) {
                float w = sm[HW1 + k * 64 + uo * 8 + i];
                acc[i]   += h0 * w;
                acc[8+i] += h1 * w;
            }
        }
        #pragma unroll
        for (int i = 0; i < 8; i++) {
            const int u = uo * 8 + i;
            sH1g[u * HP + rq]      = fmaxf(acc[i],   0.0f);
            sH1g[u * HP + rq + 16] = fmaxf(acc[8+i], 0.0f);
        }
    }
    barg(barid);

    if (lt < GROWS) {
        const int grow = rowbase + lt;     // rowbase = blockIdx*TILE_B + g*GROWS
        if (grow < B) {
            float lg[5];
            #pragma unroll
            for (int o = 0; o < 5; o++) lg[o] = sm[HB2 + o];
            for (int k = 0; k < 64; k++) {
                const float hv = sH1g[k * HP + lt];
                #pragma unroll
                for (int o = 0; o < 5; o++) lg[o] += hv * sm[HW2 + k * 5 + o];
            }
            float mx = lg[0];
            #pragma unroll
            for (int o = 1; o < 5; o++) mx = fmaxf(mx, lg[o]);
            float e[5], s = 0.0f;
            #pragma unroll
            for (int o = 0; o < 5; o++) {
                e[o] = ex2f_(1.4426950408889634f * (lg[o] - mx));
                s += e[o];
            }
            const float inv = rcpf_(s);
            #pragma unroll
            for (int o = 0; o < 5; o++) out[(size_t)grow * 5 + o] = e[o] * inv;
        }
    }
}

extern "C" void kernel_launch(void* const* d_in, const int* in_sizes, int n_in,
                              void* d_out, int out_size) {
    const float* x  = (const float*)d_in[0];
    const float* W  = (const float*)d_in[1];
    const float* U  = (const float*)d_in[2];
    const float* b  = (const float*)d_in[3];
    const float* W1 = (const float*)d_in[4];
    const float* b1 = (const float*)d_in[5];
    const float* W2 = (const float*)d_in[6];
    const float* b2 = (const float*)d_in[7];
    float* out = (float*)d_out;

    const int B = in_sizes[0] / (TSTEPS * FDIM);
    const int grid = (B + TILE_B - 1) / TILE_B;

    cudaFuncSetAttribute(lstm_kernel,
                         cudaFuncAttributeMaxDynamicSharedMemorySize, SMEM_BYTES);
    lstm_kernel<<<grid, NTHREADS, SMEM_BYTES>>>(x, W, U, b, W1, b1, W2, b2, out, B);
}

// round 13
// speedup vs baseline: 1.8635x; 1.8635x over previous
#include <cuda_runtime.h>
#include <cuda_bf16.h>
#include <cstdint>

#define TSTEPS 100
#define CROWS  128
#define THREADS 512
#define KPAD   80
#define BSTR   176         // bytes per row (88 bf16)

// smem byte offsets
#define SM_AHI0 0
#define SM_ALO0 11264          // 64*176
#define SM_AHI1 22528
#define SM_ALO1 33792
#define SM_B_HI 45056          // 256*176 = 45056
#define SM_B_LO 90112
#define SMEM_TOTAL 135168

// head phase reuses dead B region
#define SM_W1 SM_B_HI
#define SM_B1 (SM_B_HI+16384)
#define SM_W2 (SM_B_HI+16640)
#define SM_B2 (SM_B_HI+17920)
#define SM_H1 SM_B_LO          // 128*68*4 = 34816 < 45056

static __device__ __forceinline__ uint32_t s2u32(const void* p) {
    uint32_t a;
    asm("{ .reg .u64 t; cvta.to.shared.u64 t, %1; cvt.u32.u64 %0, t; }" : "=r"(a) : "l"(p));
    return a;
}
static __device__ __forceinline__ void lda4(uint32_t* r, uint32_t addr) {
    asm volatile("ldmatrix.sync.aligned.m8n8.x4.shared.b16 {%0,%1,%2,%3}, [%4];"
        : "=r"(r[0]), "=r"(r[1]), "=r"(r[2]), "=r"(r[3]) : "r"(addr));
}
static __device__ __forceinline__ void ldb2(uint32_t* r, uint32_t addr) {
    asm volatile("ldmatrix.sync.aligned.m8n8.x2.shared.b16 {%0,%1}, [%2];"
        : "=r"(r[0]), "=r"(r[1]) : "r"(addr));
}
static __device__ __forceinline__ void mma16816(float* d, const uint32_t* a, const uint32_t* bf) {
    asm volatile("mma.sync.aligned.m16n8k16.row.col.f32.bf16.bf16.f32 "
        "{%0,%1,%2,%3}, {%4,%5,%6,%7}, {%8,%9}, {%0,%1,%2,%3};"
        : "+f"(d[0]), "+f"(d[1]), "+f"(d[2]), "+f"(d[3])
        : "r"(a[0]), "r"(a[1]), "r"(a[2]), "r"(a[3]), "r"(bf[0]), "r"(bf[1]));
}
static __device__ __forceinline__ float ex2f_(float x) {
    float y; asm("ex2.approx.f32 %0, %1;" : "=f"(y) : "f"(x)); return y;
}
static __device__ __forceinline__ float rcpf_(float x) {
    float y; asm("rcp.approx.f32 %0, %1;" : "=f"(y) : "f"(x)); return y;
}
static __device__ __forceinline__ float sigf_(float x) {
    return rcpf_(1.0f + ex2f_(-1.4426950408889634f * x));
}
static __device__ __forceinline__ float tanhf_(float x) {
    return 1.0f - 2.0f * rcpf_(1.0f + ex2f_(2.8853900817779268f * x));
}
static __device__ __forceinline__ uint32_t pk2(float lo, float hi) {
    uint32_t r;  // mem layout: low16 = bf16(lo), high16 = bf16(hi)
    asm("cvt.rn.bf16x2.f32 %0, %1, %2;" : "=r"(r) : "f"(hi), "f"(lo));
    return r;
}
static __device__ __forceinline__ void barg(int id) {
    asm volatile("bar.sync %0, 256;" :: "r"(id) : "memory");
}

__global__ void __launch_bounds__(THREADS, 1)
lstm_mma_kernel(const float* __restrict__ x,  const float* __restrict__ W,
                const float* __restrict__ U,  const float* __restrict__ b,
                const float* __restrict__ W1, const float* __restrict__ b1,
                const float* __restrict__ W2, const float* __restrict__ b2,
                float* __restrict__ out, int B)
{
    extern __shared__ char smc[];
    const uint32_t sb = s2u32(smc);
    const int tid = threadIdx.x;
    const int w   = tid >> 5;
    const int lid = tid & 31;
    const int g   = (w >> 2) & 1;                 // half 0/1 (SMSP-interleaved)
    const int wh  = (w & 3) + 4 * (w >> 3);       // warp index within half 0..7
    const int wr  = wh & 3;                       // 16-row tile within half
    const int wc  = wh >> 2;                      // 0/1 -> 128-col block
    const int ht  = wh * 32 + lid;                // thread index within half
    const int barid = 1 + g;

    const uint32_t aoffHi = g ? SM_AHI1 : SM_AHI0;
    const uint32_t aoffLo = g ? SM_ALO1 : SM_ALO0;

    // ---------------- stage B = [U; W; b] hi/lo, permuted cols ----------------
    for (int idx = tid; idx < 256 * KPAD; idx += THREADS) {
        int n = idx / KPAD, k = idx % KPAD;
        int wcn = n >> 7, nn = n & 127, a = nn >> 3, id8 = nn & 7;
        int unit = 32 * wcn + 2 * a + (id8 >> 2);
        int col  = (id8 & 3) * 64 + unit;
        float v = 0.0f;
        if (k < 64)      v = U[k * 256 + col];
        else if (k < 67) v = W[(k - 64) * 256 + col];
        else if (k == 67) v = b[col];
        __nv_bfloat16 hv = __float2bfloat16(v);
        float lof = v - __bfloat162float(hv);
        *(__nv_bfloat16*)(smc + SM_B_HI + n * BSTR + k * 2) = hv;
        *(__nv_bfloat16*)(smc + SM_B_LO + n * BSTR + k * 2) = __float2bfloat16(lof);
    }
    // zero A region (h=0, x cols, pads)
    for (int idx = tid; idx < 45056 / 16; idx += THREADS)
        ((uint4*)smc)[idx] = make_uint4(0, 0, 0, 0);
    __syncthreads();
    // constant-1 column (k=67) in hi tiles
    for (int idx = tid; idx < 128; idx += THREADS) {
        int gg2 = idx >> 6, r = idx & 63;
        *(uint16_t*)(smc + (gg2 ? SM_AHI1 : SM_AHI0) + r * BSTR + 67 * 2) = 0x3F80;
    }

    // ---------------- x drivers: first 64 threads of each half ----------------
    const bool xdrv = (ht < 64);
    const float* xr = nullptr;
    if (xdrv) {
        int rg = blockIdx.x * CROWS + g * 64 + ht;
        if (rg >= B) rg = B - 1;
        xr = x + (size_t)rg * (TSTEPS * 3);
        float x0 = __ldg(xr + 0), x1 = __ldg(xr + 1), x2 = __ldg(xr + 2);
        __nv_bfloat16 h0 = __float2bfloat16(x0), h1 = __float2bfloat16(x1), h2 = __float2bfloat16(x2);
        char* ph = smc + aoffHi + ht * BSTR + 128;
        char* pl = smc + aoffLo + ht * BSTR + 128;
        *(uint32_t*)ph = pk2(__bfloat162float(h0), __bfloat162float(h1));
        *(__nv_bfloat16*)(ph + 4) = h2;
        *(uint32_t*)pl = pk2(x0 - __bfloat162float(h0), x1 - __bfloat162float(h1));
        *(__nv_bfloat16*)(pl + 4) = __float2bfloat16(x2 - __bfloat162float(h2));
    }
    __syncthreads();

    // ---------------- per-lane constants ----------------
    const uint32_t aHi = sb + aoffHi + (uint32_t)((16 * wr + (lid & 7) + 8 * ((lid >> 3) & 1)) * BSTR + ((lid >> 4) << 4));
    const uint32_t aLo = sb + aoffLo + (uint32_t)((16 * wr + (lid & 7) + 8 * ((lid >> 3) & 1)) * BSTR + ((lid >> 4) << 4));
    const uint32_t bHi = sb + SM_B_HI + (uint32_t)((128 * wc + (lid & 7)) * BSTR + (((lid >> 3) & 1) << 4));
    const uint32_t bLo = sb + SM_B_LO + (uint32_t)((128 * wc + (lid & 7)) * BSTR + (((lid >> 3) & 1) << 4));
    const int rowG = 16 * wr + (lid >> 2) + 8 * (lid & 1);
    const int upar = (lid >> 1) & 1;
    char* const hStHi = smc + aoffHi + rowG * BSTR;
    char* const hStLo = smc + aoffLo + rowG * BSTR;
    const char* const mPtr = smc + aoffHi + rowG * BSTR + 128;

    float cst[16];
    #pragma unroll
    for (int i = 0; i < 16; i++) cst[i] = 0.0f;

    float acc[64];

    // ---------------- recurrence ----------------
    #pragma unroll 1
    for (int t = 0; t < TSTEPS; t++) {
        barg(barid);     // x(t) + h(t-1) visible to this half

        // mask: any |x| != 0 — MUST ignore sign bits (-0.0 counts as zero,
        // padded entries are value*0.0 which yields -0.0 for negative values)
        uint2 mv = *(const uint2*)mPtr;
        const bool m = ((mv.x & 0x7FFF7FFFu) | (mv.y & 0x7FFFu)) != 0u;

        // prefetch x(t+1)
        float nx0 = 0.f, nx1 = 0.f, nx2 = 0.f;
        if (xdrv && t + 1 < TSTEPS) {
            nx0 = __ldg(xr + (t + 1) * 3 + 0);
            nx1 = __ldg(xr + (t + 1) * 3 + 1);
            nx2 = __ldg(xr + (t + 1) * 3 + 2);
        }

        #pragma unroll
        for (int i = 0; i < 64; i++) acc[i] = 0.0f;

        // phase 1: (Ahi + Alo) x Bhi
        #pragma unroll
        for (int k5 = 0; k5 < 5; k5++) {
            uint32_t ah[4], al[4];
            lda4(ah, aHi + k5 * 32);
            lda4(al, aLo + k5 * 32);
            #pragma unroll
            for (int a = 0; a < 16; a++) {
                uint32_t bf[2];
                ldb2(bf, bHi + a * (8 * BSTR) + k5 * 32);
                mma16816(acc + 4 * a, ah, bf);
                mma16816(acc + 4 * a, al, bf);
            }
        }
        // phase 2: Ahi x Blo
        #pragma unroll
        for (int k5 = 0; k5 < 5; k5++) {
            uint32_t ah[4];
            lda4(ah, aHi + k5 * 32);
            #pragma unroll
            for (int a = 0; a < 16; a++) {
                uint32_t bf[2];
                ldb2(bf, bLo + a * (8 * BSTR) + k5 * 32);
                mma16816(acc + 4 * a, ah, bf);
            }
        }

        barg(barid);     // all smem reads of this half's A done

        // x(t+1) store (overlaps gate math of other lanes)
        if (xdrv && t + 1 < TSTEPS) {
            __nv_bfloat16 h0 = __float2bfloat16(nx0), h1 = __float2bfloat16(nx1), h2 = __float2bfloat16(nx2);
            char* ph = smc + aoffHi + ht * BSTR + 128;
            char* pl = smc + aoffLo + ht * BSTR + 128;
            *(uint32_t*)ph = pk2(__bfloat162float(h0), __bfloat162float(h1));
            *(__nv_bfloat16*)(ph + 4) = h2;
            *(uint32_t*)pl = pk2(nx0 - __bfloat162float(h0), nx1 - __bfloat162float(h1));
            *(__nv_bfloat16*)(pl + 4) = __float2bfloat16(nx2 - __bfloat162float(h2));
        }

        // gates: redistribute quads via shfl.xor(1), then LSTM cell update
        #pragma unroll
        for (int a = 0; a < 16; a++) {
            float z0 = acc[4*a], z1 = acc[4*a+1], z2 = acc[4*a+2], z3 = acc[4*a+3];
            float p0 = __shfl_xor_sync(0xFFFFFFFFu, z0, 1);
            float p1 = __shfl_xor_sync(0xFFFFFFFFu, z1, 1);
            float p2 = __shfl_xor_sync(0xFFFFFFFFu, z2, 1);
            float p3 = __shfl_xor_sync(0xFFFFFFFFu, z3, 1);
            float zi, zf, zg, zo;
            if ((lid & 1) == 0) { zi = z0; zf = z1; zg = p0; zo = p1; }
            else                { zi = p2; zf = p3; zg = z2; zo = z3; }
            float ig = sigf_(zi);
            float fg = sigf_(zf);
            float gg = tanhf_(zg);
            float og = sigf_(zo);
            float cn = fg * cst[a] + ig * gg;
            float hn = og * tanhf_(cn);
            if (m) {
                cst[a] = cn;
                const int u = 32 * wc + 2 * a + upar;
                __nv_bfloat16 hb = __float2bfloat16(hn);
                *(__nv_bfloat16*)(hStHi + u * 2) = hb;
                *(__nv_bfloat16*)(hStLo + u * 2) =
                    __float2bfloat16(hn - __bfloat162float(hb));
            }
        }
    }
    barg(barid);
    __syncthreads();

    // ---------------- head: relu(h@W1+b1) @ W2 + b2, softmax ----------------
    for (int idx = tid; idx < 4096; idx += THREADS) ((float*)(smc + SM_W1))[idx] = W1[idx];
    for (int idx = tid; idx < 64;   idx += THREADS) ((float*)(smc + SM_B1))[idx] = b1[idx];
    for (int idx = tid; idx < 320;  idx += THREADS) ((float*)(smc + SM_W2))[idx] = W2[idx];
    if (tid < 5) ((float*)(smc + SM_B2))[tid] = b2[tid];
    __syncthreads();

    {
        const int r = tid >> 2, q = tid & 3;
        const char* AH = smc + ((r >= 64) ? SM_AHI1 : SM_AHI0) + (r & 63) * BSTR;
        const char* AL = smc + ((r >= 64) ? SM_ALO1 : SM_ALO0) + (r & 63) * BSTR;
        const float* W1s = (const float*)(smc + SM_W1);
        float a2[16];
        #pragma unroll
        for (int i = 0; i < 16; i++) a2[i] = ((const float*)(smc + SM_B1))[q * 16 + i];
        for (int kk = 0; kk < 32; kk++) {
            uint32_t ph = *(const uint32_t*)(AH + kk * 4);
            uint32_t pl = *(const uint32_t*)(AL + kk * 4);
            float h0 = __uint_as_float(ph << 16)          + __uint_as_float(pl << 16);
            float h1v = __uint_as_float(ph & 0xFFFF0000u) + __uint_as_float(pl & 0xFFFF0000u);
            const float* w0 = W1s + (2 * kk) * 64 + q * 16;
            const float* w1 = W1s + (2 * kk + 1) * 64 + q * 16;
            #pragma unroll
            for (int i = 0; i < 16; i++) a2[i] += h0 * w0[i] + h1v * w1[i];
        }
        float* H1 = (float*)(smc + SM_H1);
        #pragma unroll
        for (int i = 0; i < 16; i++) H1[r * 68 + q * 16 + i] = fmaxf(a2[i], 0.0f);
    }
    __syncthreads();

    if (tid < CROWS) {
        const int grow = blockIdx.x * CROWS + tid;
        if (grow < B) {
            const float* H1 = (const float*)(smc + SM_H1) + tid * 68;
            const float* W2s = (const float*)(smc + SM_W2);
            float lg[5];
            #pragma unroll
            for (int o = 0; o < 5; o++) lg[o] = ((const float*)(smc + SM_B2))[o];
            for (int k = 0; k < 64; k++) {
                float hv = H1[k];
                #pragma unroll
                for (int o = 0; o < 5; o++) lg[o] += hv * W2s[k * 5 + o];
            }
            float mx = lg[0];
            #pragma unroll
            for (int o = 1; o < 5; o++) mx = fmaxf(mx, lg[o]);
            float e[5], s = 0.0f;
            #pragma unroll
            for (int o = 0; o < 5; o++) { e[o] = ex2f_(1.4426950408889634f * (lg[o] - mx)); s += e[o]; }
            float inv = rcpf_(s);
            #pragma unroll
            for (int o = 0; o < 5; o++) out[(size_t)grow * 5 + o] = e[o] * inv;
        }
    }
}

extern "C" void kernel_launch(void* const* d_in, const int* in_sizes, int n_in,
                              void* d_out, int out_size) {
    const float* x  = (const float*)d_in[0];
    const float* W  = (const float*)d_in[1];
    const float* U  = (const float*)d_in[2];
    const float* b  = (const float*)d_in[3];
    const float* W1 = (const float*)d_in[4];
    const float* b1 = (const float*)d_in[5];
    const float* W2 = (const float*)d_in[6];
    const float* b2 = (const float*)d_in[7];
    float* out = (float*)d_out;

    const int B = in_sizes[0] / (TSTEPS * 3);
    const int grid = (B + CROWS - 1) / CROWS;

    cudaFuncSetAttribute(lstm_mma_kernel,
                         cudaFuncAttributeMaxDynamicSharedMemorySize, SMEM_TOTAL);
    lstm_mma_kernel<<<grid, THREADS, SMEM_TOTAL>>>(x, W, U, b, W1, b1, W2, b2, out, B);
}

// round 15
// speedup vs baseline: 2.4908x; 1.3367x over previous
#include <cuda_runtime.h>
#include <cuda_bf16.h>
#include <cstdint>

#define TSTEPS 100
#define CROWS  128
#define THREADS 512
#define KPAD   80
#define BSTR   176         // bytes per row (88 bf16)

// smem byte offsets
#define SM_AHI0 0
#define SM_ALO0 11264          // 64*176
#define SM_AHI1 22528
#define SM_ALO1 33792
#define SM_B_HI 45056          // 256*176 = 45056
#define SM_B_LO 90112
#define SMEM_TOTAL 135168

// head phase reuses dead B region
#define SM_W1 SM_B_HI
#define SM_B1 (SM_B_HI+16384)
#define SM_W2 (SM_B_HI+16640)
#define SM_B2 (SM_B_HI+17920)
#define SM_H1 SM_B_LO          // 128*68*4 = 34816 < 45056

static __device__ __forceinline__ uint32_t s2u32(const void* p) {
    uint32_t a;
    asm("{ .reg .u64 t; cvta.to.shared.u64 t, %1; cvt.u32.u64 %0, t; }" : "=r"(a) : "l"(p));
    return a;
}
static __device__ __forceinline__ void lda4(uint32_t* r, uint32_t addr) {
    asm volatile("ldmatrix.sync.aligned.m8n8.x4.shared.b16 {%0,%1,%2,%3}, [%4];"
        : "=r"(r[0]), "=r"(r[1]), "=r"(r[2]), "=r"(r[3]) : "r"(addr));
}
static __device__ __forceinline__ void ldb2(uint32_t* r, uint32_t addr) {
    asm volatile("ldmatrix.sync.aligned.m8n8.x2.shared.b16 {%0,%1}, [%2];"
        : "=r"(r[0]), "=r"(r[1]) : "r"(addr));
}
static __device__ __forceinline__ void mma16816(float* d, const uint32_t* a, const uint32_t* bf) {
    asm volatile("mma.sync.aligned.m16n8k16.row.col.f32.bf16.bf16.f32 "
        "{%0,%1,%2,%3}, {%4,%5,%6,%7}, {%8,%9}, {%0,%1,%2,%3};"
        : "+f"(d[0]), "+f"(d[1]), "+f"(d[2]), "+f"(d[3])
        : "r"(a[0]), "r"(a[1]), "r"(a[2]), "r"(a[3]), "r"(bf[0]), "r"(bf[1]));
}
static __device__ __forceinline__ float ex2f_(float x) {
    float y; asm("ex2.approx.f32 %0, %1;" : "=f"(y) : "f"(x)); return y;
}
static __device__ __forceinline__ float rcpf_(float x) {
    float y; asm("rcp.approx.f32 %0, %1;" : "=f"(y) : "f"(x)); return y;
}
static __device__ __forceinline__ float tanha_(float x) {
    float y; asm("tanh.approx.f32 %0, %1;" : "=f"(y) : "f"(x)); return y;
}
static __device__ __forceinline__ float sigt_(float x) {
    return fmaf(0.5f, tanha_(0.5f * x), 0.5f);
}
static __device__ __forceinline__ uint32_t pk2(float lo, float hi) {
    uint32_t r;  // mem layout: low16 = bf16(lo), high16 = bf16(hi)
    asm("cvt.rn.bf16x2.f32 %0, %1, %2;" : "=r"(r) : "f"(hi), "f"(lo));
    return r;
}
static __device__ __forceinline__ void barg(int id) {
    asm volatile("bar.sync %0, 256;" :: "r"(id) : "memory");
}

__global__ void __launch_bounds__(THREADS, 1)
lstm_mma_kernel(const float* __restrict__ x,  const float* __restrict__ W,
                const float* __restrict__ U,  const float* __restrict__ b,
                const float* __restrict__ W1, const float* __restrict__ b1,
                const float* __restrict__ W2, const float* __restrict__ b2,
                float* __restrict__ out, int B)
{
    extern __shared__ char smc[];
    const uint32_t sb = s2u32(smc);
    const int tid = threadIdx.x;
    const int w   = tid >> 5;
    const int lid = tid & 31;
    const int g   = (w >> 2) & 1;                 // half 0/1 (SMSP-interleaved)
    const int wh  = (w & 3) + 4 * (w >> 3);       // warp index within half 0..7
    const int wr2 = wh & 1;                       // 32-row group within half
    const int wcg = wh >> 1;                      // 64-col group 0..3
    const int ht  = wh * 32 + lid;                // thread index within half
    const int barid = 1 + g;

    const uint32_t aoffHi = g ? SM_AHI1 : SM_AHI0;
    const uint32_t aoffLo = g ? SM_ALO1 : SM_ALO0;

    // ---------------- stage B = [U; W; b] hi/lo, permuted cols ----------------
    // B row n: wcg_n = n>>6, a = (n&63)>>3, id8 = n&7
    //   unit = 16*wcg_n + 2a + (id8>>2), col = (id8&3)*64 + unit
    for (int idx = tid; idx < 256 * KPAD; idx += THREADS) {
        int n = idx / KPAD, k = idx % KPAD;
        int wcn = n >> 6, a = (n & 63) >> 3, id8 = n & 7;
        int unit = 16 * wcn + 2 * a + (id8 >> 2);
        int col  = (id8 & 3) * 64 + unit;
        float v = 0.0f;
        if (k < 64)      v = U[k * 256 + col];
        else if (k < 67) v = W[(k - 64) * 256 + col];
        else if (k == 67) v = b[col];
        __nv_bfloat16 hv = __float2bfloat16(v);
        float lof = v - __bfloat162float(hv);
        *(__nv_bfloat16*)(smc + SM_B_HI + n * BSTR + k * 2) = hv;
        *(__nv_bfloat16*)(smc + SM_B_LO + n * BSTR + k * 2) = __float2bfloat16(lof);
    }
    // zero A region (h=0, x cols, pads)
    for (int idx = tid; idx < 45056 / 16; idx += THREADS)
        ((uint4*)smc)[idx] = make_uint4(0, 0, 0, 0);
    __syncthreads();
    // constant-1 column (k=67) in hi tiles
    for (int idx = tid; idx < 128; idx += THREADS) {
        int gg2 = idx >> 6, r = idx & 63;
        *(uint16_t*)(smc + (gg2 ? SM_AHI1 : SM_AHI0) + r * BSTR + 67 * 2) = 0x3F80;
    }

    // ---------------- x drivers: first 64 threads of each half ----------------
    const bool xdrv = (ht < 64);
    const float* xr = nullptr;
    if (xdrv) {
        int rg = blockIdx.x * CROWS + g * 64 + ht;
        if (rg >= B) rg = B - 1;
        xr = x + (size_t)rg * (TSTEPS * 3);
        float x0 = __ldg(xr + 0), x1 = __ldg(xr + 1), x2 = __ldg(xr + 2);
        __nv_bfloat16 h0 = __float2bfloat16(x0), h1 = __float2bfloat16(x1), h2 = __float2bfloat16(x2);
        char* ph = smc + aoffHi + ht * BSTR + 128;
        char* pl = smc + aoffLo + ht * BSTR + 128;
        *(uint32_t*)ph = pk2(__bfloat162float(h0), __bfloat162float(h1));
        *(__nv_bfloat16*)(ph + 4) = h2;
        *(uint32_t*)pl = pk2(x0 - __bfloat162float(h0), x1 - __bfloat162float(h1));
        *(__nv_bfloat16*)(pl + 4) = __float2bfloat16(x2 - __bfloat162float(h2));
    }
    __syncthreads();

    // ---------------- per-lane constants ----------------
    // A lane addr (tile s=0; s=1 at +16*BSTR): rows 32*wr2 + (lid&7) + 8*((lid>>3)&1)
    const int arow = 32 * wr2 + (lid & 7) + 8 * ((lid >> 3) & 1);
    const uint32_t aHi0 = sb + aoffHi + (uint32_t)(arow * BSTR + ((lid >> 4) << 4));
    const uint32_t aLo0 = sb + aoffLo + (uint32_t)(arow * BSTR + ((lid >> 4) << 4));
    // B lane addr: row n = 64*wcg + 8a + (lid&7)
    const uint32_t bHi = sb + SM_B_HI + (uint32_t)((64 * wcg + (lid & 7)) * BSTR + (((lid >> 3) & 1) << 4));
    const uint32_t bLo = sb + SM_B_LO + (uint32_t)((64 * wcg + (lid & 7)) * BSTR + (((lid >> 3) & 1) << 4));
    // gate lane geometry
    const int rowG = 32 * wr2 + (lid >> 2) + 8 * (lid & 1);  // tile s adds +16s
    const int upar = (lid >> 1) & 1;
    char* const hStHi = smc + aoffHi + rowG * BSTR;
    char* const hStLo = smc + aoffLo + rowG * BSTR;
    const char* const mPtr = smc + aoffHi + rowG * BSTR + 128;

    float cst[16];
    #pragma unroll
    for (int i = 0; i < 16; i++) cst[i] = 0.0f;

    float acc[64];

    // ---------------- recurrence ----------------
    #pragma unroll 1
    for (int t = 0; t < TSTEPS; t++) {
        barg(barid);     // x(t) + h(t-1) visible to this half

        // masks for this lane's 2 rows (sign bits ignored: -0.0 counts as zero)
        uint2 mv0 = *(const uint2*)mPtr;
        uint2 mv1 = *(const uint2*)(mPtr + 16 * BSTR);
        const bool m0 = ((mv0.x & 0x7FFF7FFFu) | (mv0.y & 0x7FFFu)) != 0u;
        const bool m1 = ((mv1.x & 0x7FFF7FFFu) | (mv1.y & 0x7FFFu)) != 0u;

        // prefetch x(t+1)
        float nx0 = 0.f, nx1 = 0.f, nx2 = 0.f;
        if (xdrv && t + 1 < TSTEPS) {
            nx0 = __ldg(xr + (t + 1) * 3 + 0);
            nx1 = __ldg(xr + (t + 1) * 3 + 1);
            nx2 = __ldg(xr + (t + 1) * 3 + 2);
        }

        #pragma unroll
        for (int i = 0; i < 64; i++) acc[i] = 0.0f;

        // phase 1: (Ahi + Alo) x Bhi, both 16-row tiles
        #pragma unroll
        for (int k5 = 0; k5 < 5; k5++) {
            uint32_t ah0[4], ah1[4], al0[4], al1[4];
            lda4(ah0, aHi0 + k5 * 32);
            lda4(ah1, aHi0 + 16 * BSTR + k5 * 32);
            lda4(al0, aLo0 + k5 * 32);
            lda4(al1, aLo0 + 16 * BSTR + k5 * 32);
            #pragma unroll
            for (int a = 0; a < 8; a++) {
                uint32_t bf[2];
                ldb2(bf, bHi + a * (8 * BSTR) + k5 * 32);
                mma16816(acc + 4 * a,      ah0, bf);
                mma16816(acc + 4 * a,      al0, bf);
                mma16816(acc + 32 + 4 * a, ah1, bf);
                mma16816(acc + 32 + 4 * a, al1, bf);
            }
        }
        // phase 2: Ahi x Blo
        #pragma unroll
        for (int k5 = 0; k5 < 5; k5++) {
            uint32_t ah0[4], ah1[4];
            lda4(ah0, aHi0 + k5 * 32);
            lda4(ah1, aHi0 + 16 * BSTR + k5 * 32);
            #pragma unroll
            for (int a = 0; a < 8; a++) {
                uint32_t bf[2];
                ldb2(bf, bLo + a * (8 * BSTR) + k5 * 32);
                mma16816(acc + 4 * a,      ah0, bf);
                mma16816(acc + 32 + 4 * a, ah1, bf);
            }
        }

        barg(barid);     // all smem reads of this half's A done

        // x(t+1) store (overlaps gate math of other lanes)
        if (xdrv && t + 1 < TSTEPS) {
            __nv_bfloat16 h0 = __float2bfloat16(nx0), h1 = __float2bfloat16(nx1), h2 = __float2bfloat16(nx2);
            char* ph = smc + aoffHi + ht * BSTR + 128;
            char* pl = smc + aoffLo + ht * BSTR + 128;
            *(uint32_t*)ph = pk2(__bfloat162float(h0), __bfloat162float(h1));
            *(__nv_bfloat16*)(ph + 4) = h2;
            *(uint32_t*)pl = pk2(nx0 - __bfloat162float(h0), nx1 - __bfloat162float(h1));
            *(__nv_bfloat16*)(pl + 4) = __float2bfloat16(nx2 - __bfloat162float(h2));
        }

        // gates: per tile s, per ntile a — shfl.xor(1) assembles gate quads
        #pragma unroll
        for (int s = 0; s < 2; s++) {
            const bool m = s ? m1 : m0;
            #pragma unroll
            for (int a = 0; a < 8; a++) {
                const int ai = s * 32 + 4 * a;
                float z0 = acc[ai], z1 = acc[ai+1], z2 = acc[ai+2], z3 = acc[ai+3];
                float p0 = __shfl_xor_sync(0xFFFFFFFFu, z0, 1);
                float p1 = __shfl_xor_sync(0xFFFFFFFFu, z1, 1);
                float p2 = __shfl_xor_sync(0xFFFFFFFFu, z2, 1);
                float p3 = __shfl_xor_sync(0xFFFFFFFFu, z3, 1);
                float zi, zf, zg, zo;
                if ((lid & 1) == 0) { zi = z0; zf = z1; zg = p0; zo = p1; }
                else                { zi = p2; zf = p3; zg = z2; zo = z3; }
                float ig = sigt_(zi);
                float fg = sigt_(zf);
                float gg = tanha_(zg);
                float og = sigt_(zo);
                float cn = fg * cst[s*8+a] + ig * gg;
                float hn = og * tanha_(cn);
                if (m) {
                    cst[s*8+a] = cn;
                    const int u = 16 * wcg + 2 * a + upar;
                    const int roff = (s * 16) * BSTR + u * 2;
                    __nv_bfloat16 hb = __float2bfloat16(hn);
                    *(__nv_bfloat16*)(hStHi + roff) = hb;
                    *(__nv_bfloat16*)(hStLo + roff) =
                        __float2bfloat16(hn - __bfloat162float(hb));
                }
            }
        }
    }
    barg(barid);
    __syncthreads();

    // ---------------- head: relu(h@W1+b1) @ W2 + b2, softmax ----------------
    for (int idx = tid; idx < 4096; idx += THREADS) ((float*)(smc + SM_W1))[idx] = W1[idx];
    for (int idx = tid; idx < 64;   idx += THREADS) ((float*)(smc + SM_B1))[idx] = b1[idx];
    for (int idx = tid; idx < 320;  idx += THREADS) ((float*)(smc + SM_W2))[idx] = W2[idx];
    if (tid < 5) ((float*)(smc + SM_B2))[tid] = b2[tid];
    __syncthreads();

    {
        const int r = tid >> 2, q = tid & 3;
        const char* AH = smc + ((r >= 64) ? SM_AHI1 : SM_AHI0) + (r & 63) * BSTR;
        const char* AL = smc + ((r >= 64) ? SM_ALO1 : SM_ALO0) + (r & 63) * BSTR;
        const float* W1s = (const float*)(smc + SM_W1);
        float a2[16];
        #pragma unroll
        for (int i = 0; i < 16; i++) a2[i] = ((const float*)(smc + SM_B1))[q * 16 + i];
        for (int kk = 0; kk < 32; kk++) {
            uint32_t ph = *(const uint32_t*)(AH + kk * 4);
            uint32_t pl = *(const uint32_t*)(AL + kk * 4);
            float h0 = __uint_as_float(ph << 16)          + __uint_as_float(pl << 16);
            float h1v = __uint_as_float(ph & 0xFFFF0000u) + __uint_as_float(pl & 0xFFFF0000u);
            const float* w0 = W1s + (2 * kk) * 64 + q * 16;
            const float* w1 = W1s + (2 * kk + 1) * 64 + q * 16;
            #pragma unroll
            for (int i = 0; i < 16; i++) a2[i] += h0 * w0[i] + h1v * w1[i];
        }
        float* H1 = (float*)(smc + SM_H1);
        #pragma unroll
        for (int i = 0; i < 16; i++) H1[r * 68 + q * 16 + i] = fmaxf(a2[i], 0.0f);
    }
    __syncthreads();

    if (tid < CROWS) {
        const int grow = blockIdx.x * CROWS + tid;
        if (grow < B) {
            const float* H1 = (const float*)(smc + SM_H1) + tid * 68;
            const float* W2s = (const float*)(smc + SM_W2);
            float lg[5];
            #pragma unroll
            for (int o = 0; o < 5; o++) lg[o] = ((const float*)(smc + SM_B2))[o];
            for (int k = 0; k < 64; k++) {
                float hv = H1[k];
                #pragma unroll
                for (int o = 0; o < 5; o++) lg[o] += hv * W2s[k * 5 + o];
            }
            float mx = lg[0];
            #pragma unroll
            for (int o = 1; o < 5; o++) mx = fmaxf(mx, lg[o]);
            float e[5], s = 0.0f;
            #pragma unroll
            for (int o = 0; o < 5; o++) { e[o] = ex2f_(1.4426950408889634f * (lg[o] - mx)); s += e[o]; }
            float inv = rcpf_(s);
            #pragma unroll
            for (int o = 0; o < 5; o++) out[(size_t)grow * 5 + o] = e[o] * inv;
        }
    }
}

extern "C" void kernel_launch(void* const* d_in, const int* in_sizes, int n_in,
                              void* d_out, int out_size) {
    const float* x  = (const float*)d_in[0];
    const float* W  = (const float*)d_in[1];
    const float* U  = (const float*)d_in[2];
    const float* b  = (const float*)d_in[3];
    const float* W1 = (const float*)d_in[4];
    const float* b1 = (const float*)d_in[5];
    const float* W2 = (const float*)d_in[6];
    const float* b2 = (const float*)d_in[7];
    float* out = (float*)d_out;

    const int B = in_sizes[0] / (TSTEPS * 3);
    const int grid = (B + CROWS - 1) / CROWS;

    cudaFuncSetAttribute(lstm_mma_kernel,
                         cudaFuncAttributeMaxDynamicSharedMemorySize, SMEM_TOTAL);
    lstm_mma_kernel<<<grid, THREADS, SMEM_TOTAL>>>(x, W, U, b, W1, b1, W2, b2, out, B);
}